// round 5
// baseline (speedup 1.0000x reference)
#include <cuda_runtime.h>
#include <math.h>

#define EPSF 1e-7f

static constexpr int B = 16, H = 224, W = 224, C = 32;
static constexpr int SAMPLE = H * W * C;            // 1,605,632
static constexpr int BH = B * H;                    // 3584
static constexpr int NPLANE = B * H * W * C;        // 25,690,112

// Scratch: 4 horizontal-sum planes (h2,h4,h8,h16), 411 MB device global.
__device__ float g_h[4][NPLANE];
__device__ unsigned g_mn[B];
__device__ unsigned g_mx[B];

// Monotonic unsigned encoding of float for atomicMin/Max
__device__ __forceinline__ unsigned fenc(float f) {
    unsigned u = __float_as_uint(f);
    return (u & 0x80000000u) ? ~u : (u | 0x80000000u);
}
__device__ __forceinline__ float fdec(unsigned u) {
    return __uint_as_float((u & 0x80000000u) ? (u ^ 0x80000000u) : ~u);
}

__global__ void k0_init() {
    int i = threadIdx.x;
    if (i < B) { g_mn[i] = 0xFFFFFFFFu; g_mx[i] = 0u; }
}

// K1: per-sample min/max. grid = (56, B), 256 threads.
__global__ void __launch_bounds__(256) k1_minmax(const float4* __restrict__ x) {
    int b = blockIdx.y;
    const float4* xb = x + (size_t)b * (SAMPLE / 4);
    int tid = blockIdx.x * 256 + threadIdx.x;         // 0..14335
    float mn = INFINITY, mx = -INFINITY;
    for (int i = tid; i < SAMPLE / 4; i += 56 * 256) {
        float4 v = xb[i];
        mn = fminf(mn, fminf(fminf(v.x, v.y), fminf(v.z, v.w)));
        mx = fmaxf(mx, fmaxf(fmaxf(v.x, v.y), fmaxf(v.z, v.w)));
    }
    #pragma unroll
    for (int o = 16; o; o >>= 1) {
        mn = fminf(mn, __shfl_xor_sync(0xffffffffu, mn, o));
        mx = fmaxf(mx, __shfl_xor_sync(0xffffffffu, mx, o));
    }
    __shared__ float smn[8], smx[8];
    if ((threadIdx.x & 31) == 0) { smn[threadIdx.x >> 5] = mn; smx[threadIdx.x >> 5] = mx; }
    __syncthreads();
    if (threadIdx.x < 32) {
        mn = (threadIdx.x < 8) ? smn[threadIdx.x] : INFINITY;
        mx = (threadIdx.x < 8) ? smx[threadIdx.x] : -INFINITY;
        #pragma unroll
        for (int o = 4; o; o >>= 1) {
            mn = fminf(mn, __shfl_xor_sync(0xffffffffu, mn, o));
            mx = fmaxf(mx, __shfl_xor_sync(0xffffffffu, mx, o));
        }
        if (threadIdx.x == 0) {
            atomicMin(&g_mn[b], fenc(mn));
            atomicMax(&g_mx[b], fenc(mx));
        }
    }
}

// K2: horizontal box sums (sliding windows, register ring). One thread per (b,h,c),
// streaming w. 448 blocks x 256 threads = 114688 threads.
__global__ void __launch_bounds__(256) k2_hpass(const float* __restrict__ x) {
    int g = blockIdx.x * 256 + threadIdx.x;
    int c  = g & 31;
    int bh = g >> 5;                 // 0..3583
    int b  = bh / H;

    float mn  = fdec(g_mn[b]);
    float inv = 1.0f / (fdec(g_mx[b]) - mn + EPSF);

    const float* xr = x + (size_t)bh * W * C + c;    // row base, w-stride = C
    float* o0 = g_h[0] + (size_t)bh * W * C + c;
    float* o1 = g_h[1] + (size_t)bh * W * C + c;
    float* o2 = g_h[2] + (size_t)bh * W * C + c;
    float* o3 = g_h[3] + (size_t)bh * W * C + c;

    float ring[16];
    #pragma unroll
    for (int i = 0; i < 16; i++) ring[i] = 0.0f;
    float H2 = 0.f, H4 = 0.f, H8 = 0.f, H16 = 0.f;

    #pragma unroll 1
    for (int it = 0; it < 15; ++it) {
        #pragma unroll
        for (int j = 0; j < 16; ++j) {
            int w  = it * 16 + j - 16;
            int wn = w + 8;
            float xn = 0.0f;
            if ((unsigned)wn < (unsigned)W) xn = (__ldg(xr + (size_t)wn * C) - mn) * inv;
            // window updates: H_r(w) = H_r(w-1) + xs(w+hi_r) - xs(w-lo_r-1)
            H16 += xn               - ring[(j + 8)  & 15];
            H8  += ring[(j+4)  &15] - ring[(j + 12) & 15];
            H4  += ring[(j+2)  &15] - ring[(j + 14) & 15];
            H2  += ring[(j+1)  &15] - ring[(j + 15) & 15];
            ring[(j + 8) & 15] = xn;
            if (w >= 0) {
                size_t o = (size_t)w * C;
                o0[o] = H2; o1[o] = H4; o2[o] = H8; o3[o] = H16;
            }
        }
    }
}

// K3: vertical box sums + slope + BN. One thread per (b,w,c), streaming h.
__global__ void __launch_bounds__(256) k3_vpass(
    const float* __restrict__ gamma, const float* __restrict__ beta,
    const float* __restrict__ mmean, const float* __restrict__ mvar,
    float* __restrict__ out)
{
    int g = blockIdx.x * 256 + threadIdx.x;
    int c  = g & 31;
    int bw = g >> 5;                  // b*W + w
    int b  = bw / W;
    int w  = bw - b * W;

    float sbn = gamma[c] * rsqrtf(mvar[c] + 1e-3f);
    float bbn = beta[c] - mmean[c] * sbn;

    size_t base = ((size_t)b * H * W + w) * C + c;   // index at h=0
    const int hs = W * C;                             // 7168
    const float* p2  = g_h[0];
    const float* p4  = g_h[1];
    const float* p8  = g_h[2];
    const float* p16 = g_h[3];

    float r2a[2], r4a[4], r8a[8], r16a[16];
    #pragma unroll
    for (int i = 0; i < 2; i++)  r2a[i]  = 0.f;
    #pragma unroll
    for (int i = 0; i < 4; i++)  r4a[i]  = 0.f;
    #pragma unroll
    for (int i = 0; i < 8; i++)  r8a[i]  = 0.f;
    #pragma unroll
    for (int i = 0; i < 16; i++) r16a[i] = 0.f;
    float V2 = 0.f, V4 = 0.f, V8 = 0.f, V16 = 0.f;

    #pragma unroll 1
    for (int it = 0; it < 15; ++it) {
        #pragma unroll
        for (int j = 0; j < 16; ++j) {
            int h = it * 16 + j - 16;
            float n2 = 0.f, n4 = 0.f, n8 = 0.f, n16 = 0.f;
            int h1 = h + 1, h2i = h + 2, h4i = h + 4, h8i = h + 8;
            if ((unsigned)h1  < (unsigned)H) n2  = __ldg(p2  + base + (size_t)h1  * hs);
            if ((unsigned)h2i < (unsigned)H) n4  = __ldg(p4  + base + (size_t)h2i * hs);
            if ((unsigned)h4i < (unsigned)H) n8  = __ldg(p8  + base + (size_t)h4i * hs);
            if ((unsigned)h8i < (unsigned)H) n16 = __ldg(p16 + base + (size_t)h8i * hs);

            V2  += n2  - r2a [(j + 1) & 1];  r2a [(j + 1) & 1]  = n2;
            V4  += n4  - r4a [(j + 2) & 3];  r4a [(j + 2) & 3]  = n4;
            V8  += n8  - r8a [(j + 4) & 7];  r8a [(j + 4) & 7]  = n8;
            V16 += n16 - r16a[(j + 8) & 15]; r16a[(j + 8) & 15] = n16;

            if (h >= 0) {
                float m2  = fmaxf(V2,  0.f) + EPSF;
                float m4  = fmaxf(V4,  0.f) + EPSF;
                float m8  = fmaxf(V8,  0.f) + EPSF;
                float m16 = fmaxf(V16, 0.f) + EPSF;
                // alpha = 0.1 * log2( m16^3*m8 / (m2^3*m4) )
                float num = m16 * m16 * m16 * m8;
                float den = m2 * m2 * m2 * m4;
                float alpha = 0.1f * __log2f(num / den);
                out[base + (size_t)h * hs] = alpha * sbn + bbn;
            }
        }
    }
}

extern "C" void kernel_launch(void* const* d_in, const int* in_sizes, int n_in,
                              void* d_out, int out_size) {
    const float* x     = (const float*)d_in[0];
    const float* gamma = (const float*)d_in[1];
    const float* beta  = (const float*)d_in[2];
    const float* mmean = (const float*)d_in[3];
    const float* mvar  = (const float*)d_in[4];
    float* out = (float*)d_out;

    k0_init<<<1, 32>>>();
    dim3 g1(56, B);
    k1_minmax<<<g1, 256>>>((const float4*)x);
    k2_hpass<<<448, 256>>>(x);
    k3_vpass<<<448, 256>>>(gamma, beta, mmean, mvar, out);
}

// round 6
// speedup vs baseline: 1.2633x; 1.2633x over previous
#include <cuda_runtime.h>
#include <math.h>

#define EPSF 1e-7f

static constexpr int B = 16, H = 224, W = 224, C = 32;
static constexpr int TW = 16;      // output columns per block
static constexpr int CH = 112;     // output rows per block
static constexpr int QD = 18;      // prefix ring depth (rows)
static constexpr int QROW = 32 * 33;            // one prefix row: 32 l-entries, stride 33, 32 c
static constexpr int QBYTES = QD * QROW * 4;    // 76032 B dynamic smem

__device__ unsigned g_mn[B];
__device__ unsigned g_mx[B];

// Monotonic unsigned encoding of float for atomicMin/Max
__device__ __forceinline__ unsigned fenc(float f) {
    unsigned u = __float_as_uint(f);
    return (u & 0x80000000u) ? ~u : (u | 0x80000000u);
}
__device__ __forceinline__ float fdec(unsigned u) {
    return __uint_as_float((u & 0x80000000u) ? (u ^ 0x80000000u) : ~u);
}

__global__ void k0_init() {
    int i = threadIdx.x;
    if (i < B) { g_mn[i] = 0xFFFFFFFFu; g_mx[i] = 0u; }
}

// K1: per-sample min/max. grid = (56, B), 256 threads.
__global__ void __launch_bounds__(256) k1_minmax(const float4* __restrict__ x) {
    int b = blockIdx.y;
    const float4* xb = x + (size_t)b * (H * W * C / 4);
    int tid = blockIdx.x * 256 + threadIdx.x;
    float mn = INFINITY, mx = -INFINITY;
    for (int i = tid; i < H * W * C / 4; i += 56 * 256) {
        float4 v = xb[i];
        mn = fminf(mn, fminf(fminf(v.x, v.y), fminf(v.z, v.w)));
        mx = fmaxf(mx, fmaxf(fmaxf(v.x, v.y), fmaxf(v.z, v.w)));
    }
    #pragma unroll
    for (int o = 16; o; o >>= 1) {
        mn = fminf(mn, __shfl_xor_sync(0xffffffffu, mn, o));
        mx = fmaxf(mx, __shfl_xor_sync(0xffffffffu, mx, o));
    }
    __shared__ float smn[8], smx[8];
    if ((threadIdx.x & 31) == 0) { smn[threadIdx.x >> 5] = mn; smx[threadIdx.x >> 5] = mx; }
    __syncthreads();
    if (threadIdx.x < 32) {
        mn = (threadIdx.x < 8) ? smn[threadIdx.x] : INFINITY;
        mx = (threadIdx.x < 8) ? smx[threadIdx.x] : -INFINITY;
        #pragma unroll
        for (int o = 4; o; o >>= 1) {
            mn = fminf(mn, __shfl_xor_sync(0xffffffffu, mn, o));
            mx = fmaxf(mx, __shfl_xor_sync(0xffffffffu, mx, o));
        }
        if (threadIdx.x == 0) {
            atomicMin(&g_mn[b], fenc(mn));
            atomicMax(&g_mx[b], fenc(mx));
        }
    }
}

// Fused: horizontal prefix sums (rolling 18-row ring in SMEM) + vertical sliding
// box accumulators + slope + BN. One pass over x, one write of out.
// Block = (w-tile, h-chunk, b). 512 threads = 16 w-outputs x 32 c.
__global__ void __launch_bounds__(512, 2) k_fused(
    const float* __restrict__ x,
    const float* __restrict__ gamma, const float* __restrict__ beta,
    const float* __restrict__ mmean, const float* __restrict__ mvar,
    float* __restrict__ out)
{
    extern __shared__ float Q[];   // [QD][32 l][stride 33] channel-inner

    const int tid = threadIdx.x;
    const int c = tid & 31;        // channel (= lane)
    const int q = tid >> 5;        // w-output index within tile (= warp id)
    const int w0 = blockIdx.x * TW;
    const int h0 = blockIdx.y * CH;
    const int b  = blockIdx.z;

    const float mn  = fdec(g_mn[b]);
    const float inv = 1.0f / (fdec(g_mx[b]) - mn + EPSF);
    const float mni = mn * inv;

    const float sbn = gamma[c] * rsqrtf(mvar[c] + 1e-3f);
    const float bbn = fmaf(-mmean[c], sbn, beta[c]);

    // Pre-zero the ring: unwritten slots must read as 0 during warm-up.
    for (int i = tid; i < QD * QROW; i += 512) Q[i] = 0.0f;

    const int g0 = w0 - 8 + q;     // global col for l = q  (l==0 stays 0: exclusive base)
    const int g1 = g0 + 16;        // global col for l = q+16
    const size_t rs = (size_t)W * C;
    const float* xb = x + (size_t)b * H * rs + c;

    // prefetch row a = h0 - 8 (t = 0)
    float p0 = 0.0f, p1 = 0.0f;
    {
        int a = h0 - 8;
        if ((unsigned)a < (unsigned)H) {
            const float* xr = xb + (size_t)a * rs;
            if (q != 0 && (unsigned)g0 < (unsigned)W) p0 = fmaf(__ldg(xr + g0 * C), inv, -mni);
            if ((unsigned)g1 < (unsigned)W)           p1 = fmaf(__ldg(xr + g1 * C), inv, -mni);
        }
    }

    // precomputed column offsets for phase 3 (lw = q + 8)
    const int lw = q + 8;
    const int o16p = (lw + 8) * 33 + c, o16m = (lw - 8) * 33 + c;
    const int o8p  = (lw + 4) * 33 + c, o8m  = (lw - 4) * 33 + c;
    const int o4p  = (lw + 2) * 33 + c, o4m  = (lw - 2) * 33 + c;
    const int o2p  = (lw + 1) * 33 + c, o2m  = (lw - 1) * 33 + c;

    float V2 = 0.f, V4 = 0.f, V8 = 0.f, V16 = 0.f;
    int s = 0;                      // slot = t % QD

    __syncthreads();                // ring zero-fill complete

    #pragma unroll 1
    for (int t = 0; t < CH + 16; ++t) {
        // ---- phase 1: store prefetched raw xs row into slot s ----
        float* Qs = Q + s * QROW;
        Qs[q * 33 + c] = p0;
        Qs[(q + 16) * 33 + c] = p1;
        __syncthreads();

        // ---- phase 2: inclusive prefix along l, warp q handles channels q, q+16 ----
        #pragma unroll
        for (int cc = 0; cc < 2; ++cc) {
            const int ch = q + cc * 16;
            float v = Qs[c * 33 + ch];          // lane c plays role of l
            #pragma unroll
            for (int o = 1; o < 32; o <<= 1) {
                float n = __shfl_up_sync(0xffffffffu, v, o);
                if (c >= o) v += n;
            }
            Qs[c * 33 + ch] = v;
        }

        // ---- prefetch next row (hidden behind syncB + phase 3) ----
        p0 = 0.0f; p1 = 0.0f;
        {
            int a = h0 - 7 + t;
            if ((unsigned)a < (unsigned)H) {
                const float* xr = xb + (size_t)a * rs;
                if (q != 0 && (unsigned)g0 < (unsigned)W) p0 = fmaf(__ldg(xr + g0 * C), inv, -mni);
                if ((unsigned)g1 < (unsigned)W)           p1 = fmaf(__ldg(xr + g1 * C), inv, -mni);
            }
        }
        __syncthreads();

        // ---- phase 3: vertical sliding updates + output ----
        {
            int s4  = s - 4;  if (s4  < 0) s4  += QD;
            int s6  = s - 6;  if (s6  < 0) s6  += QD;
            int s7  = s - 7;  if (s7  < 0) s7  += QD;
            int s9  = s - 9;  if (s9  < 0) s9  += QD;
            int s10 = s - 10; if (s10 < 0) s10 += QD;
            int s12 = s - 12; if (s12 < 0) s12 += QD;
            int s16 = s - 16; if (s16 < 0) s16 += QD;

            const float* r0  = Q + s   * QROW;
            const float* r4  = Q + s4  * QROW;
            const float* r6  = Q + s6  * QROW;
            const float* r7  = Q + s7  * QROW;
            const float* r9  = Q + s9  * QROW;
            const float* r10 = Q + s10 * QROW;
            const float* r12 = Q + s12 * QROW;
            const float* r16 = Q + s16 * QROW;

            V16 += (r0 [o16p] - r0 [o16m]) - (r16[o16p] - r16[o16m]);
            V8  += (r4 [o8p]  - r4 [o8m])  - (r12[o8p]  - r12[o8m]);
            V4  += (r6 [o4p]  - r6 [o4m])  - (r10[o4p]  - r10[o4m]);
            V2  += (r7 [o2p]  - r7 [o2m])  - (r9 [o2p]  - r9 [o2m]);

            if (t >= 16) {
                float m2  = fmaxf(V2,  0.f) + EPSF;
                float m4  = fmaxf(V4,  0.f) + EPSF;
                float m8  = fmaxf(V8,  0.f) + EPSF;
                float m16 = fmaxf(V16, 0.f) + EPSF;
                float alpha = 0.1f * (__log2f(m16 * m16 * m16 * m8)
                                    - __log2f(m2 * m2 * m2 * m4));
                int h = h0 + t - 16;
                out[((size_t)(b * H + h) * W + (w0 + q)) * C + c] = fmaf(alpha, sbn, bbn);
            }
        }
        s = (s + 1 == QD) ? 0 : s + 1;
    }
}

extern "C" void kernel_launch(void* const* d_in, const int* in_sizes, int n_in,
                              void* d_out, int out_size) {
    const float* x     = (const float*)d_in[0];
    const float* gamma = (const float*)d_in[1];
    const float* beta  = (const float*)d_in[2];
    const float* mmean = (const float*)d_in[3];
    const float* mvar  = (const float*)d_in[4];
    float* out = (float*)d_out;

    cudaFuncSetAttribute(k_fused, cudaFuncAttributeMaxDynamicSharedMemorySize, QBYTES);

    k0_init<<<1, 32>>>();
    dim3 g1(56, B);
    k1_minmax<<<g1, 256>>>((const float4*)x);
    dim3 gf(W / TW, H / CH, B);   // 14 x 2 x 16 = 448 blocks
    k_fused<<<gf, 512, QBYTES>>>(x, gamma, beta, mmean, mvar, out);
}

// round 7
// speedup vs baseline: 1.3886x; 1.0991x over previous
#include <cuda_runtime.h>
#include <math.h>

#define EPSF 1e-7f

static constexpr int B = 16, H = 224, W = 224, C = 32;
static constexpr int TW = 16;      // output columns per block
static constexpr int CH = 112;     // output rows per block
static constexpr int QD = 24;      // prefix ring depth (rows); 4-row super-iter needs >= 24
static constexpr int QROW = 1024;  // floats per ring row: 32 l-entries x 32 c, XOR-swizzled
static constexpr int QBYTES = QD * QROW * 4;   // 98304 B dynamic smem -> 2 CTAs/SM

__device__ unsigned g_mn[B];
__device__ unsigned g_mx[B];

// Monotonic unsigned encoding of float for atomicMin/Max
__device__ __forceinline__ unsigned fenc(float f) {
    unsigned u = __float_as_uint(f);
    return (u & 0x80000000u) ? ~u : (u | 0x80000000u);
}
__device__ __forceinline__ float fdec(unsigned u) {
    return __uint_as_float((u & 0x80000000u) ? (u ^ 0x80000000u) : ~u);
}

__global__ void k0_init() {
    int i = threadIdx.x;
    if (i < B) { g_mn[i] = 0xFFFFFFFFu; g_mx[i] = 0u; }
}

// K1: per-sample min/max. grid = (56, B), 256 threads.
__global__ void __launch_bounds__(256) k1_minmax(const float4* __restrict__ x) {
    int b = blockIdx.y;
    const float4* xb = x + (size_t)b * (H * W * C / 4);
    int tid = blockIdx.x * 256 + threadIdx.x;
    float mn = INFINITY, mx = -INFINITY;
    for (int i = tid; i < H * W * C / 4; i += 56 * 256) {
        float4 v = xb[i];
        mn = fminf(mn, fminf(fminf(v.x, v.y), fminf(v.z, v.w)));
        mx = fmaxf(mx, fmaxf(fmaxf(v.x, v.y), fmaxf(v.z, v.w)));
    }
    #pragma unroll
    for (int o = 16; o; o >>= 1) {
        mn = fminf(mn, __shfl_xor_sync(0xffffffffu, mn, o));
        mx = fmaxf(mx, __shfl_xor_sync(0xffffffffu, mx, o));
    }
    __shared__ float smn[8], smx[8];
    if ((threadIdx.x & 31) == 0) { smn[threadIdx.x >> 5] = mn; smx[threadIdx.x >> 5] = mx; }
    __syncthreads();
    if (threadIdx.x < 32) {
        mn = (threadIdx.x < 8) ? smn[threadIdx.x] : INFINITY;
        mx = (threadIdx.x < 8) ? smx[threadIdx.x] : -INFINITY;
        #pragma unroll
        for (int o = 4; o; o >>= 1) {
            mn = fminf(mn, __shfl_xor_sync(0xffffffffu, mn, o));
            mx = fmaxf(mx, __shfl_xor_sync(0xffffffffu, mx, o));
        }
        if (threadIdx.x == 0) {
            atomicMin(&g_mn[b], fenc(mn));
            atomicMax(&g_mx[b], fenc(mx));
        }
    }
}

// Fused kernel: 4-row super-iterations, XOR-swizzled prefix ring, deep register prefetch.
// Block = (w-tile TW=16, h-chunk CH=112, b). 512 threads = 16 warps(w-output) x 32 lanes(c).
__global__ void __launch_bounds__(512, 2) k_fused(
    const float* __restrict__ x,
    const float* __restrict__ gamma, const float* __restrict__ beta,
    const float* __restrict__ mmean, const float* __restrict__ mvar,
    float* __restrict__ out)
{
    extern __shared__ float Q[];   // [QD][32 l][32 c], word(l,c) = l*32 + ((l+c)&31)

    const int tid = threadIdx.x;
    const int c = tid & 31;        // channel (= lane)
    const int q = tid >> 5;        // w-output index within tile (= warp id)
    const int w0 = blockIdx.x * TW;
    const int h0 = blockIdx.y * CH;
    const int b  = blockIdx.z;

    const float mn  = fdec(g_mn[b]);
    const float inv = 1.0f / (fdec(g_mx[b]) - mn + EPSF);
    const float mni = mn * inv;

    const float sbn = gamma[c] * rsqrtf(mvar[c] + 1e-3f);
    const float bbn = fmaf(-mmean[c], sbn, beta[c]);

    // Pre-zero the ring: unwritten slots must read as 0 during warm-up.
    for (int i = tid; i < QD * QROW; i += 512) Q[i] = 0.0f;

    // ---- addressing ----
    const int colA = w0 - 8 + q;       // l = q      (l==0 forced 0: exclusive prefix base)
    const int colB = w0 + 8 + q;       // l = q + 16
    const bool okA = (q != 0) && ((unsigned)colA < (unsigned)W);
    const bool okB = ((unsigned)colB < (unsigned)W);
    const long long offA = (long long)colA * C;
    const long long offB = (long long)colB * C;
    const float* xb = x + (size_t)b * H * W * C + c;
    const int rs = W * C;              // 7168

    // swizzled word offsets. P1 store words; P3 read words around lw = q+8.
    #define SWZ(l) ((l) * 32 + (((l) + c) & 31))
    const int wA   = SWZ(q);           // == o16m
    const int wB   = SWZ(q + 16);      // == o16p
    const int o8p  = SWZ(q + 12), o8m = SWZ(q + 4);
    const int o4p  = SWZ(q + 10), o4m = SWZ(q + 6);
    const int o2p  = SWZ(q + 9),  o2m = SWZ(q + 7);
    #undef SWZ

    // output base pointer at t=0 (h = h0 + t - 16); only dereferenced for t>=16.
    float* outP = out + ((long long)(b * H + h0 - 16) * W + (w0 + q)) * C + c;

    // ---- register prefetch: 4 rows x 2 values, one super-iteration of lead ----
    float pf0[4], pf1[4];
    #define PREFETCH(T0)                                                      \
        _Pragma("unroll")                                                     \
        for (int r = 0; r < 4; ++r) {                                         \
            int a = h0 - 8 + (T0) + r;                                        \
            float v0 = 0.0f, v1 = 0.0f;                                       \
            if ((unsigned)a < (unsigned)H) {                                  \
                const float* xr = xb + (long long)a * rs;                     \
                if (okA) v0 = fmaf(__ldg(xr + offA), inv, -mni);              \
                if (okB) v1 = fmaf(__ldg(xr + offB), inv, -mni);              \
            }                                                                 \
            pf0[r] = v0; pf1[r] = v1;                                         \
        }

    float V2 = 0.f, V4 = 0.f, V8 = 0.f, V16 = 0.f;
    int s = 0;                      // ring slot of first row of current super-iter

    PREFETCH(0);
    __syncthreads();                // ring zero-fill complete

    #pragma unroll 1
    for (int k = 0; k < (CH + 16) / 4; ++k) {
        const int t0 = 4 * k;

        // ---- P1: store 4 prefetched raw rows into slots s..s+3 ----
        #pragma unroll
        for (int r = 0; r < 4; ++r) {
            float* Qs = Q + (s + r) * QROW;
            Qs[wA] = pf0[r];
            Qs[wB] = pf1[r];
        }
        __syncthreads();

        // ---- P2: in-place inclusive prefix along l; warp q owns channels q, q+16.
        //      8 independent chains per warp -> shuffle latency hidden by ILP. ----
        #pragma unroll
        for (int r = 0; r < 4; ++r) {
            float* Qs = Q + (s + r) * QROW;
            #pragma unroll
            for (int cc = 0; cc < 2; ++cc) {
                const int ch = q + cc * 16;
                const int wd = c * 32 + ((c + ch) & 31);   // lane c plays role of l
                float v = Qs[wd];
                #pragma unroll
                for (int o = 1; o < 32; o <<= 1) {
                    float n = __shfl_up_sync(0xffffffffu, v, o);
                    if (c >= o) v += n;
                }
                Qs[wd] = v;
            }
        }

        // ---- prefetch next super-iteration (full super-iter of lead time) ----
        PREFETCH(t0 + 4);
        __syncthreads();

        // ---- P3: vertical sliding updates + outputs for rows t0..t0+3 ----
        #pragma unroll
        for (int r = 0; r < 4; ++r) {
            const int t = t0 + r;
            const int u = s + r;                   // 0..23, no wrap needed
            int u4  = u - 4;  if (u4  < 0) u4  += QD;
            int u6  = u - 6;  if (u6  < 0) u6  += QD;
            int u7  = u - 7;  if (u7  < 0) u7  += QD;
            int u9  = u - 9;  if (u9  < 0) u9  += QD;
            int u10 = u - 10; if (u10 < 0) u10 += QD;
            int u12 = u - 12; if (u12 < 0) u12 += QD;
            int u16 = u - 16; if (u16 < 0) u16 += QD;

            const float* r0  = Q + u   * QROW;
            const float* r4  = Q + u4  * QROW;
            const float* r6  = Q + u6  * QROW;
            const float* r7  = Q + u7  * QROW;
            const float* r9  = Q + u9  * QROW;
            const float* r10 = Q + u10 * QROW;
            const float* r12 = Q + u12 * QROW;
            const float* r16 = Q + u16 * QROW;

            V16 += (r0 [wB]  - r0 [wA])  - (r16[wB]  - r16[wA]);
            V8  += (r4 [o8p] - r4 [o8m]) - (r12[o8p] - r12[o8m]);
            V4  += (r6 [o4p] - r6 [o4m]) - (r10[o4p] - r10[o4m]);
            V2  += (r7 [o2p] - r7 [o2m]) - (r9 [o2p] - r9 [o2m]);

            if (t >= 16) {
                float m2  = fmaxf(V2,  0.f) + EPSF;
                float m4  = fmaxf(V4,  0.f) + EPSF;
                float m8  = fmaxf(V8,  0.f) + EPSF;
                float m16 = fmaxf(V16, 0.f) + EPSF;
                float alpha = 0.1f * (__log2f(m16 * m16 * m16 * m8)
                                    - __log2f(m2 * m2 * m2 * m4));
                outP[(long long)t * rs] = fmaf(alpha, sbn, bbn);
            }
        }
        s += 4; if (s == QD) s = 0;
    }
    #undef PREFETCH
}

extern "C" void kernel_launch(void* const* d_in, const int* in_sizes, int n_in,
                              void* d_out, int out_size) {
    const float* x     = (const float*)d_in[0];
    const float* gamma = (const float*)d_in[1];
    const float* beta  = (const float*)d_in[2];
    const float* mmean = (const float*)d_in[3];
    const float* mvar  = (const float*)d_in[4];
    float* out = (float*)d_out;

    cudaFuncSetAttribute(k_fused, cudaFuncAttributeMaxDynamicSharedMemorySize, QBYTES);

    k0_init<<<1, 32>>>();
    dim3 g1(56, B);
    k1_minmax<<<g1, 256>>>((const float4*)x);
    dim3 gf(W / TW, H / CH, B);   // 14 x 2 x 16 = 448 blocks
    k_fused<<<gf, 512, QBYTES>>>(x, gamma, beta, mmean, mvar, out);
}